// round 17
// baseline (speedup 1.0000x reference)
#include <cuda_runtime.h>
#include <cuda_fp16.h>
#include <cstdint>

// NCC loss, 9x9 box, SAME zero pad, n=81 (matches reference conv).
// Round 17: factored taps with register-resident X via warp shuffle.
//   box9 = 3-sum of 3-sums, but the per-column product fields X(u) =
//   {P=(a,c), PP, PQ, GQ} stay in REGISTERS: lane u gets X(u+1), X(u+2) via
//   __shfl_down_sync; lanes 30/31 recompute cross-warp neighbors from the
//   fp32 rows (already barrier-protected -> no extra sync). Only the 3-sums
//   T3[u] hit smem (1 STS.128, contiguous, conflict-free).
//   Taps: 3 LDS.128 + 8 HADD2 per pixel (was 9x(LDS.64+PRMT+4 HFMA2) = 54).
//   smem traffic DROPS vs R13 (T3 write 17B + tap read 48B vs 8B + 72B).
//   T3 entries that mix rows / use clamped tail reads are never consumed
//   (tap index max = j*136+133 < row boundary at j*136+134).
// Numerics identical to R14's X/T path (measured rel_err 4.3e-7).
// Chassis byte-identical to R13 (53.8us): depth-4 cp.async wait_group 2,
// uniform commit, 2 barriers/stage, fp16 ring + fp32 S exact-cancel slide,
// merged epilogue, __launch_bounds__(128,6), grid 4x8x32.
// Deterministic fused reduction (fixed-order, wrapping atomicInc).

#define WW 512
#define HH 512
#define NB 32
#define COLS 128
#define STRIPH 64
#define NBLK (4 * 8 * 32)   // 1024 blocks
#define NSTAGE 24           // 72 row-steps / 3 rows per stage
#define VECS_PER_STAGE 306  // 9 row-images * 34 float4
#define UNITS 408           // 3 rows * 136 cols per stage

__device__ float        g_partials[NBLK];
__device__ unsigned int g_count = 0;

__device__ __forceinline__ void cp16(uint32_t dst, const float* src, bool ok) {
    asm volatile("cp.async.cg.shared.global [%0], [%1], 16, %2;"
                 :: "r"(dst), "l"(src), "r"(ok ? 16 : 0) : "memory");
}
__device__ __forceinline__ void cp_commit() {
    asm volatile("cp.async.commit_group;" ::: "memory");
}
__device__ __forceinline__ void cp_wait2() {
    asm volatile("cp.async.wait_group 2;" ::: "memory");
}
__device__ __forceinline__ __half2 h2u(unsigned v) {
    return *reinterpret_cast<__half2*>(&v);
}
__device__ __forceinline__ unsigned u2h(__half2 h) {
    return *reinterpret_cast<unsigned*>(&h);
}

// Build packed product fields for column-unit w of the staged fp32 block.
__device__ __forceinline__ void buildX(const float* Rf32, int w,
                                       unsigned& x0, unsigned& x1,
                                       unsigned& x2, unsigned& x3) {
    const float av = Rf32[w];
    const float cv = Rf32[w + 408];
    const float fv = Rf32[w + 816];
    const __half2 P = __floats2half2_rn(av, cv);
    const __half2 Q = __floats2half2_rn(fv, fv);
    const __half2 G = __floats2half2_rn(fv, 1.0f);
    x0 = u2h(P);                 // (a,  c)
    x1 = u2h(__hmul2(P, P));     // (aa, cc)
    x2 = u2h(__hmul2(P, Q));     // (af, cf)
    x3 = u2h(__hmul2(G, Q));     // (ff, f)
}

__global__ __launch_bounds__(128, 6)
void ncc_fused(const float* __restrict__ img1,
               const float* __restrict__ img2,
               const float* __restrict__ fus,
               float* __restrict__ out)
{
    const int tid   = threadIdx.x;
    const int lane  = tid & 31;
    const int xbase = blockIdx.x * COLS;
    const int ybase = blockIdx.y * STRIPH;
    const int b     = blockIdx.z;

    const size_t base = (size_t)b * (size_t)(HH * WW);
    const float* p1 = img1 + base;
    const float* p2 = img2 + base;
    const float* pf = fus  + base;

    // staged fp32: [buf][img*3+row][136]; img-major so flat u / u+408 / u+816
    __shared__ float rows[4][9][136];
    // per-stage 3-col sums of product fields: uint4 {SP, SPP, SPQ, SGQ}
    __shared__ __align__(16) uint4 T3[UNITS];
    __shared__ float red[4];
    __shared__ int   lastflag;

    const uint32_t smem_rows = (uint32_t)__cvta_generic_to_shared(&rows[0][0][0]);

    // ---- loop-invariant staging descriptors (3 vecs per thread) ----
    const float* pb[3];
    int          joff[3];
    uint32_t     doff[3];
    bool         cokv[3];
    bool         act[3];
#pragma unroll
    for (int it = 0; it < 3; ++it) {
        const int i  = tid + 128 * it;
        act[it]      = (i < VECS_PER_STAGE);
        const int ii  = act[it] ? i : 0;
        const int ri  = ii / 34;            // row-image 0..8 = img*3 + jj
        const int vec = ii - ri * 34;
        const int img = ri / 3;
        joff[it]      = ri - img * 3;
        const int gx  = xbase - 4 + vec * 4;
        const bool ck = (gx >= 0) && (gx <= WW - 4);
        cokv[it]      = ck;
        const float* p = (img == 0) ? p1 : ((img == 1) ? p2 : pf);
        pb[it]        = p + (ck ? gx : 0);
        doff[it]      = (uint32_t)((ri * 136 + vec * 4) * 4);
    }

    auto stage = [&](int s, int buf) {
        const int r0 = ybase - 4 + 3 * s;
        const uint32_t bb = smem_rows + (uint32_t)(buf * (9 * 136 * 4));
#pragma unroll
        for (int it = 0; it < 3; ++it) {
            if (act[it]) {
                const int  r   = r0 + joff[it];
                const bool rok = ((unsigned)r < (unsigned)HH);
                const int  rc  = rok ? r : 0;
                cp16(bb + doff[it], pb[it] + (size_t)rc * WW, rok && cokv[it]);
            }
        }
    };

    // ring stores A1..A4 (4 half2 per slot = 36 regs); S fp32
    __half2 ring[9][4];
    float S[8];
#pragma unroll
    for (int j = 0; j < 9; ++j)
#pragma unroll
        for (int q = 0; q < 4; ++q) ring[j][q] = __floats2half2_rn(0.0f, 0.0f);
#pragma unroll
    for (int q = 0; q < 8; ++q) S[q] = 0.0f;

    float acc = 0.0f;
    const float inv_n = 1.0f / 81.0f;

    stage(0, 0); cp_commit();
    stage(1, 1); cp_commit();
    stage(2, 2); cp_commit();

    for (int a = 0; a < 8; ++a) {
#pragma unroll
        for (int g = 0; g < 3; ++g) {
            const int s   = 3 * a + g;
            const int buf = s & 3;
            // pending groups: s, s+1, s+2 (later ones may be empty commits)
            cp_wait2();
            __syncthreads();   // stage-s fp32 visible; prev iter's T3 reads done

            // ---- conversion: fp32 -> T3 (register X + shuffle 3-sums) ----
            {
                const float* Rf32 = &rows[buf][0][0];
#pragma unroll
                for (int it = 0; it < 4; ++it) {
                    const int u  = tid + 128 * it;
                    const int uc = (u < UNITS) ? u : (UNITS - 1);

                    unsigned x0, x1, x2, x3;
                    buildX(Rf32, uc, x0, x1, x2, x3);

                    // neighbors via shuffle (all lanes participate)
                    unsigned a0 = __shfl_down_sync(0xffffffffu, x0, 1);
                    unsigned a1 = __shfl_down_sync(0xffffffffu, x1, 1);
                    unsigned a2 = __shfl_down_sync(0xffffffffu, x2, 1);
                    unsigned a3 = __shfl_down_sync(0xffffffffu, x3, 1);
                    unsigned b0 = __shfl_down_sync(0xffffffffu, x0, 2);
                    unsigned b1 = __shfl_down_sync(0xffffffffu, x1, 2);
                    unsigned b2 = __shfl_down_sync(0xffffffffu, x2, 2);
                    unsigned b3 = __shfl_down_sync(0xffffffffu, x3, 2);

                    // lanes 30/31: cross-warp neighbors -> recompute from fp32
                    if (lane >= 30) {
                        const int w2 = (uc + 2 <= UNITS - 1) ? uc + 2 : UNITS - 1;
                        if (lane == 31) {
                            const int w1 = (uc + 1 <= UNITS - 1) ? uc + 1
                                                                 : UNITS - 1;
                            buildX(Rf32, w1, a0, a1, a2, a3);
                        }
                        buildX(Rf32, w2, b0, b1, b2, b3);
                    }

                    if (u < UNITS) {
                        uint4 t;
                        t.x = u2h(__hadd2(__hadd2(h2u(x0), h2u(a0)), h2u(b0)));
                        t.y = u2h(__hadd2(__hadd2(h2u(x1), h2u(a1)), h2u(b1)));
                        t.z = u2h(__hadd2(__hadd2(h2u(x2), h2u(a2)), h2u(b2)));
                        t.w = u2h(__hadd2(__hadd2(h2u(x3), h2u(a3)), h2u(b3)));
                        T3[u] = t;
                    }
                }
            }
            __syncthreads();   // T3 visible to all

            if (s + 3 < NSTAGE) stage(s + 3, (s + 3) & 3);
            cp_commit();       // unconditional: uniform group accounting

#pragma unroll
            for (int j = 0; j < 3; ++j) {
                const int slot = 3 * g + j;     // static 0..8 == (9a+slot) % 9
                const int bse  = j * 136 + tid;

                // ---- 9-tap = 3-sum of T3 ----
                const uint4 t0 = T3[bse];
                const uint4 t1 = T3[bse + 3];
                const uint4 t2 = T3[bse + 6];
                const __half2 A1 = __hadd2(__hadd2(h2u(t0.x), h2u(t1.x)), h2u(t2.x));
                const __half2 A2 = __hadd2(__hadd2(h2u(t0.y), h2u(t1.y)), h2u(t2.y));
                const __half2 A3 = __hadd2(__hadd2(h2u(t0.z), h2u(t1.z)), h2u(t2.z));
                const __half2 A4 = __hadd2(__hadd2(h2u(t0.w), h2u(t1.w)), h2u(t2.w));

                // ---- dequantize new and retiring entries (identical path) ----
                const float2 u1 = __half22float2(A1);   // (Sa,  Sc)
                const float2 u2 = __half22float2(A2);   // (Saa, Scc)
                const float2 u3 = __half22float2(A3);   // (Saf, Scf)
                const float2 u4 = __half22float2(A4);   // (Sff, Sf)
                const float2 o1 = __half22float2(ring[slot][0]);
                const float2 o2 = __half22float2(ring[slot][1]);
                const float2 o3 = __half22float2(ring[slot][2]);
                const float2 o4 = __half22float2(ring[slot][3]);

                // ---- vertical slide in fp32 (exact cancellation) ----
                S[0] += u1.x - o1.x;  S[3] += u1.y - o1.y;
                S[1] += u2.x - o2.x;  S[4] += u2.y - o2.y;
                S[2] += u3.x - o3.x;  S[5] += u3.y - o3.y;
                S[7] += u4.x - o4.x;  S[6] += u4.y - o4.y;

                ring[slot][0] = A1;
                ring[slot][1] = A2;
                ring[slot][2] = A3;
                ring[slot][3] = A4;

                // ---- emit output row (row-step i = 9a+slot >= 8) ----
                if (a > 0 || slot >= 8) {
                    const float mA = S[0] * inv_n;
                    const float mB = S[3] * inv_n;
                    const float mJ = S[6] * inv_n;
                    const float crossA = fmaf(-mA, S[6], S[2]);
                    const float varA   = fmaf(-mA, S[0], S[1]);
                    const float varJ   = fmaf(-mJ, S[6], S[7]);
                    const float crossB = fmaf(-mB, S[6], S[5]);
                    const float varB   = fmaf(-mB, S[3], S[4]);
                    const float dA = fmaf(varA, varJ, 1e-5f);
                    const float dB = fmaf(varB, varJ, 1e-5f);
                    // ccA + ccB = (crossA^2*dB + crossB^2*dA) / (dA*dB)
                    const float num = fmaf(crossB * crossB, dA,
                                           crossA * crossA * dB);
                    const float rcp = __fdividef(1.0f, dA * dB);
                    acc = fmaf(-num, rcp, acc + 2.0f);   // += 2 - (ccA+ccB)
                }
            }
            // no bottom barrier: next iteration's top __syncthreads protects
            // the fp32 buffer ring (depth 4) and T3 reuse
        }
    }

    // ---- deterministic block reduction ----
#pragma unroll
    for (int off = 16; off > 0; off >>= 1)
        acc += __shfl_xor_sync(0xffffffffu, acc, off);
    if ((tid & 31) == 0) red[tid >> 5] = acc;
    __syncthreads();

    const int bidx = (blockIdx.z * 8 + blockIdx.y) * 4 + blockIdx.x;
    if (tid == 0) {
        g_partials[bidx] = (red[0] + red[1]) + (red[2] + red[3]);
        __threadfence();
        unsigned int old = atomicInc(&g_count, NBLK - 1);  // wraps: graph-replay safe
        lastflag = (old == NBLK - 1);
    }
    __syncthreads();

    if (lastflag) {
        float v = 0.0f;
#pragma unroll
        for (int m = 0; m < NBLK / 128; ++m)
            v += g_partials[tid + 128 * m];
#pragma unroll
        for (int off = 16; off > 0; off >>= 1)
            v += __shfl_xor_sync(0xffffffffu, v, off);
        if ((tid & 31) == 0) red[tid >> 5] = v;
        __syncthreads();
        if (tid == 0) {
            const float tot = (red[0] + red[1]) + (red[2] + red[3]);
            // mean(combined) = sum(2*combined) * 0.5 / 2^23 = tot * 2^-24
            out[0] = tot * 5.9604644775390625e-08f;
        }
    }
}

extern "C" void kernel_launch(void* const* d_in, const int* in_sizes, int n_in,
                              void* d_out, int out_size)
{
    (void)in_sizes; (void)n_in; (void)out_size;
    const float* img1 = (const float*)d_in[0];
    const float* img2 = (const float*)d_in[1];
    const float* fus  = (const float*)d_in[2];

    dim3 grid(4, 8, NB);   // 1024 blocks
    ncc_fused<<<grid, 128>>>(img1, img2, fus, (float*)d_out);
}